// round 12
// baseline (speedup 1.0000x reference)
#include <cuda_runtime.h>
#include <cuda_fp16.h>
#include <cstdint>

#define S_LEN 2048
#define D_MODEL 2048
#define NB 2
#define NH 16
#define DHD 128
#define M_ROWS 4096

// ---------------- scratch (static __device__, allocation-guard safe) -------
__device__ __align__(16) __half g_xh[(size_t)M_ROWS * D_MODEL];
__device__ __align__(16) __half g_wh[(size_t)4 * D_MODEL * D_MODEL];  // q,k,v,o
__device__ __align__(16) __half g_qh[(size_t)M_ROWS * D_MODEL];       // [b][h][s][d]
__device__ __align__(16) __half g_kh[(size_t)M_ROWS * D_MODEL];
__device__ __align__(16) __half g_vh[(size_t)M_ROWS * D_MODEL];
__device__ __align__(16) __half g_aoh[(size_t)M_ROWS * D_MODEL];      // [b*s][h*128+d]

// ---------------- PTX helpers ----------------------------------------------
__device__ __forceinline__ void ldsm4(uint32_t* r, uint32_t a) {
    asm volatile("ldmatrix.sync.aligned.m8n8.x4.shared.b16 {%0,%1,%2,%3}, [%4];"
                 : "=r"(r[0]), "=r"(r[1]), "=r"(r[2]), "=r"(r[3]) : "r"(a));
}
__device__ __forceinline__ void ldsm4t(uint32_t* r, uint32_t a) {
    asm volatile("ldmatrix.sync.aligned.m8n8.x4.trans.shared.b16 {%0,%1,%2,%3}, [%4];"
                 : "=r"(r[0]), "=r"(r[1]), "=r"(r[2]), "=r"(r[3]) : "r"(a));
}
__device__ __forceinline__ void mma16(float* c, const uint32_t* a, uint32_t b0, uint32_t b1) {
    asm volatile(
        "mma.sync.aligned.m16n8k16.row.col.f32.f16.f16.f32 "
        "{%0,%1,%2,%3}, {%4,%5,%6,%7}, {%8,%9}, {%0,%1,%2,%3};"
        : "+f"(c[0]), "+f"(c[1]), "+f"(c[2]), "+f"(c[3])
        : "r"(a[0]), "r"(a[1]), "r"(a[2]), "r"(a[3]), "r"(b0), "r"(b1));
}
__device__ __forceinline__ void cpa16(uint32_t saddr, const void* gptr) {
    asm volatile("cp.async.cg.shared.global [%0], [%1], 16;" :: "r"(saddr), "l"(gptr));
}
#define CP_COMMIT asm volatile("cp.async.commit_group;" ::: "memory")
#define CP_WAIT0  asm volatile("cp.async.wait_group 0;" ::: "memory")
#define CP_WAIT1  asm volatile("cp.async.wait_group 1;" ::: "memory")

__device__ __forceinline__ uint32_t h2u(float a, float b) {
    __half2 h = __floats2half2_rn(a, b);
    return *reinterpret_cast<uint32_t*>(&h);
}

// ---------------- pre-pass: fp32 -> fp16 ------------------------------------
__global__ __launch_bounds__(256) void cvt_h_kernel(
    const float* __restrict__ x,
    const float* __restrict__ wq, const float* __restrict__ wk,
    const float* __restrict__ wv, const float* __restrict__ wo)
{
    const int z = blockIdx.z;
    const float* src;
    __half* dst;
    int n4;
    if (z == 0)      { src = x;  dst = g_xh; n4 = M_ROWS * D_MODEL / 4; }
    else if (z == 1) { src = wq; dst = g_wh;                                 n4 = D_MODEL * D_MODEL / 4; }
    else if (z == 2) { src = wk; dst = g_wh + (size_t)1 * D_MODEL * D_MODEL; n4 = D_MODEL * D_MODEL / 4; }
    else if (z == 3) { src = wv; dst = g_wh + (size_t)2 * D_MODEL * D_MODEL; n4 = D_MODEL * D_MODEL / 4; }
    else             { src = wo; dst = g_wh + (size_t)3 * D_MODEL * D_MODEL; n4 = D_MODEL * D_MODEL / 4; }

    int idx = blockIdx.x * 256 + threadIdx.x;
    if (idx < n4) {
        float4 v = ((const float4*)src)[idx];
        __half2* d2 = (__half2*)dst + (size_t)idx * 2;
        d2[0] = __floats2half2_rn(v.x, v.y);
        d2[1] = __floats2half2_rn(v.z, v.w);
    }
}

// ---------------- GEMM: UNCHANGED from R10 (known-good) ---------------------
// 128x128 block, BK=64, 8 warps 2x4, warp 64x32, 3-stage ring, 1 sync/chunk.
#define GEMM_SMEM (3 * 32768) /* 98304 */

__global__ __launch_bounds__(256) void gemm_h_kernel(
    float* __restrict__ Oout,
    const float* __restrict__ fc, const float* __restrict__ fs,
    int is_final)
{
    extern __shared__ __align__(16) char smraw[];
    const uint32_t sb = (uint32_t)__cvta_generic_to_shared(smraw);

    const int mode = is_final ? 3 : (int)blockIdx.z;
    const __half* A = is_final ? g_aoh : g_xh;
    const __half* W = g_wh + (size_t)mode * D_MODEL * D_MODEL;

    const int tid = threadIdx.x;
    const int warp = tid >> 5, lane = tid & 31;
    const int wm = warp >> 2, wn = warp & 3;
    const int g = lane >> 2, tg = lane & 3;
    const int bm = blockIdx.y, bn = blockIdx.x;

    const __half* Ab = A + (size_t)(bm * 128) * D_MODEL;
    const __half* Bb = W + (size_t)(bn * 128) * D_MODEL;

    float acc[4][4][4];
#pragma unroll
    for (int mi = 0; mi < 4; mi++)
#pragma unroll
        for (int ni = 0; ni < 4; ni++)
#pragma unroll
            for (int j = 0; j < 4; j++) acc[mi][ni][j] = 0.f;

    auto docopy = [&](int kc) {
        const uint32_t s0 = sb + (uint32_t)(kc % 3) * 32768;
#pragma unroll
        for (int i = 0; i < 8; i++) {
            int li = i * 256 + tid;
            if (li < 1024) {
                int r = li >> 3, c = li & 7;
                cpa16(s0 + r * 128 + ((c ^ (r & 7)) << 4),
                      Ab + (size_t)r * D_MODEL + kc * 64 + c * 8);
            } else {
                int l2 = li - 1024;
                int r = l2 >> 3, c = l2 & 7;
                cpa16(s0 + 16384 + r * 128 + ((c ^ (r & 7)) << 4),
                      Bb + (size_t)r * D_MODEL + kc * 64 + c * 8);
            }
        }
        CP_COMMIT;
    };

    const int nk = D_MODEL / 64;
    docopy(0);
    docopy(1);

    for (int kc = 0; kc < nk; kc++) {
        if (kc == nk - 1) { CP_WAIT0; } else { CP_WAIT1; }
        __syncthreads();

        if (kc + 2 < nk) docopy(kc + 2);

        const uint32_t sA = sb + (uint32_t)(kc % 3) * 32768;
        const uint32_t sBs = sA + 16384;

#pragma unroll
        for (int kk = 0; kk < 4; kk++) {
            uint32_t bf[4][2];
#pragma unroll
            for (int nip = 0; nip < 2; nip++) {
                int row = wn * 32 + nip * 16 + (lane & 7) + ((lane >> 4) << 3);
                int c8 = kk * 2 + ((lane >> 3) & 1);
                uint32_t r4[4];
                ldsm4(r4, sBs + row * 128 + ((c8 ^ (row & 7)) << 4));
                bf[2 * nip][0] = r4[0]; bf[2 * nip][1] = r4[1];
                bf[2 * nip + 1][0] = r4[2]; bf[2 * nip + 1][1] = r4[3];
            }
#pragma unroll
            for (int mi = 0; mi < 4; mi++) {
                int row = wm * 64 + mi * 16 + (lane & 15);
                int c8 = kk * 2 + (lane >> 4);
                uint32_t a4[4];
                ldsm4(a4, sA + row * 128 + ((c8 ^ (row & 7)) << 4));
#pragma unroll
                for (int ni = 0; ni < 4; ni++)
                    mma16(acc[mi][ni], a4, bf[ni][0], bf[ni][1]);
            }
        }
    }

#pragma unroll
    for (int mi = 0; mi < 4; mi++) {
#pragma unroll
        for (int ni = 0; ni < 4; ni++) {
            int m0 = bm * 128 + wm * 64 + mi * 16 + g;
            int n0 = bn * 128 + wn * 32 + ni * 8 + tg * 2;
#pragma unroll
            for (int h2 = 0; h2 < 2; h2++) {
                int m = m0 + h2 * 8;
                float e = acc[mi][ni][h2 * 2];
                float o = acc[mi][ni][h2 * 2 + 1];
                if (mode == 3) {
                    *(float2*)(Oout + (size_t)m * D_MODEL + n0) = make_float2(e, o);
                } else {
                    int b = m >> 11, s = m & 2047;
                    int hh = n0 >> 7, d = n0 & 127;
                    if (mode != 2) {
                        float c  = fc[s * 64 + (d >> 1)];
                        float sn = fs[s * 64 + (d >> 1)];
                        float e2 = e * c - o * sn;
                        float o2 = e * sn + o * c;
                        e = e2; o = o2;
                    }
                    __half* dst = (mode == 0) ? g_qh : (mode == 1) ? g_kh : g_vh;
                    size_t idx = ((size_t)(b * NH + hh) * S_LEN + s) * DHD + d;
                    *(__half2*)(dst + idx) = __floats2half2_rn(e, o);
                }
            }
        }
    }
}

// ---------------- Flash attention: Q in SMEM, 2 CTAs/SM ---------------------
// Block: (qb, bh). 256 threads, 8 warps x 16 q-rows. BQ=128, BKV=64.
// Q tile (128x128h, 32KB) loaded once via cp.async into smem; A-fragments
// fetched per k-step via ldmatrix (frees 32 regs vs register-resident Q ->
// <=128 regs -> 2 CTAs/SM with 96KB smem).
// smem: [KV slot0 32KB][KV slot1 32KB][Q 32KB]
#define ATT_SMEM 98304

__global__ __launch_bounds__(256, 2) void attn_h_kernel()
{
    extern __shared__ __align__(16) char smraw[];
    const uint32_t sb = (uint32_t)__cvta_generic_to_shared(smraw);
    const uint32_t Qs = sb + 65536;

    const int bh = blockIdx.y;
    const int qb = blockIdx.x;
    const int tid = threadIdx.x;
    const int warp = tid >> 5, lane = tid & 31;
    const int g = lane >> 2, tg = lane & 3;
    const int r0 = qb * 128 + warp * 16 + g;

    const __half* qb_p = g_qh + (size_t)bh * S_LEN * DHD + (size_t)(qb * 128) * DHD;
    const __half* kb_p = g_kh + (size_t)bh * S_LEN * DHD;
    const __half* vb_p = g_vh + (size_t)bh * S_LEN * DHD;

    // ---- Q tile -> smem (swizzled like K), part of cp.async group 0 ----
#pragma unroll
    for (int i = 0; i < 8; i++) {
        int li = i * 256 + tid;            // 2048 16B-chunks: 128 rows x 16
        int r = li >> 4, c16 = li & 15;
        cpa16(Qs + r * 256 + ((c16 ^ (r & 7)) << 4),
              qb_p + (size_t)r * DHD + c16 * 8);
    }

    float oacc[16][4];
#pragma unroll
    for (int ni = 0; ni < 16; ni++)
#pragma unroll
        for (int j = 0; j < 4; j++) oacc[ni][j] = 0.f;

    float m0v = -1e30f, m1v = -1e30f, l0 = 0.f, l1 = 0.f;
    const float scale = 0.08838834764831845f;

    auto docopy = [&](int t, int buf) {
        const uint32_t s0 = sb + buf * 32768;
        const int kv0 = t * 64;
#pragma unroll
        for (int i = 0; i < 8; i++) {
            int li = i * 256 + tid;
            if (i < 4) {
                int r = li >> 4, c16 = li & 15;
                cpa16(s0 + r * 256 + ((c16 ^ (r & 7)) << 4),
                      kb_p + (size_t)(kv0 + r) * DHD + c16 * 8);
            } else {
                int l2 = li - 1024;
                int r = l2 >> 4, c16 = l2 & 15;
                cpa16(s0 + 16384 + r * 256 + ((c16 ^ (r & 7)) << 4),
                      vb_p + (size_t)(kv0 + r) * DHD + c16 * 8);
            }
        }
    };

    const int nkv = 2 * (qb + 1);
    docopy(0, 0);
    CP_COMMIT;                    // group0 = Q tile + KV tile 0

    for (int t = 0; t < nkv; t++) {
        if (t + 1 < nkv) { docopy(t + 1, (t + 1) & 1); CP_COMMIT; CP_WAIT1; }
        else             { CP_WAIT0; }
        __syncthreads();

        const uint32_t Kb = sb + (t & 1) * 32768;
        const uint32_t Vb = Kb + 16384;
        const int kv0 = t * 64;

        if (kv0 <= qb * 128 + warp * 16 + 15) {
            // ---- S = Q K^T (Q fragments from smem via ldmatrix) ----
            float s[8][4];
#pragma unroll
            for (int ni = 0; ni < 8; ni++)
#pragma unroll
                for (int j = 0; j < 4; j++) s[ni][j] = 0.f;

#pragma unroll
            for (int kk = 0; kk < 8; kk++) {
                uint32_t qa[4];
                {
                    int row = warp * 16 + (lane & 15);
                    int c16 = kk * 2 + (lane >> 4);
                    ldsm4(qa, Qs + row * 256 + ((c16 ^ (row & 7)) << 4));
                }
#pragma unroll
                for (int nip = 0; nip < 4; nip++) {
                    int row = nip * 16 + (lane & 7) + ((lane >> 4) << 3);
                    int c16 = kk * 2 + ((lane >> 3) & 1);
                    uint32_t r4[4];
                    ldsm4(r4, Kb + row * 256 + ((c16 ^ (row & 7)) << 4));
                    mma16(s[2 * nip],     qa, r4[0], r4[1]);
                    mma16(s[2 * nip + 1], qa, r4[2], r4[3]);
                }
            }

            float mn0 = -1e30f, mn1 = -1e30f;
#pragma unroll
            for (int ni = 0; ni < 8; ni++) {
                int c = kv0 + ni * 8 + tg * 2;
                s[ni][0] = (c     <= r0)     ? s[ni][0] * scale : -1e30f;
                s[ni][1] = (c + 1 <= r0)     ? s[ni][1] * scale : -1e30f;
                s[ni][2] = (c     <= r0 + 8) ? s[ni][2] * scale : -1e30f;
                s[ni][3] = (c + 1 <= r0 + 8) ? s[ni][3] * scale : -1e30f;
                mn0 = fmaxf(mn0, fmaxf(s[ni][0], s[ni][1]));
                mn1 = fmaxf(mn1, fmaxf(s[ni][2], s[ni][3]));
            }
            mn0 = fmaxf(mn0, __shfl_xor_sync(0xffffffffu, mn0, 1));
            mn0 = fmaxf(mn0, __shfl_xor_sync(0xffffffffu, mn0, 2));
            mn1 = fmaxf(mn1, __shfl_xor_sync(0xffffffffu, mn1, 1));
            mn1 = fmaxf(mn1, __shfl_xor_sync(0xffffffffu, mn1, 2));

            float mt0 = fmaxf(m0v, mn0), mt1 = fmaxf(m1v, mn1);
            float a0 = __expf(m0v - mt0), a1 = __expf(m1v - mt1);
            m0v = mt0; m1v = mt1;

            float rs0 = 0.f, rs1 = 0.f;
#pragma unroll
            for (int ni = 0; ni < 8; ni++) {
                s[ni][0] = __expf(s[ni][0] - mt0);
                s[ni][1] = __expf(s[ni][1] - mt0);
                s[ni][2] = __expf(s[ni][2] - mt1);
                s[ni][3] = __expf(s[ni][3] - mt1);
                rs0 += s[ni][0] + s[ni][1];
                rs1 += s[ni][2] + s[ni][3];
            }
            rs0 += __shfl_xor_sync(0xffffffffu, rs0, 1);
            rs0 += __shfl_xor_sync(0xffffffffu, rs0, 2);
            rs1 += __shfl_xor_sync(0xffffffffu, rs1, 1);
            rs1 += __shfl_xor_sync(0xffffffffu, rs1, 2);
            l0 = l0 * a0 + rs0;
            l1 = l1 * a1 + rs1;

#pragma unroll
            for (int ni = 0; ni < 16; ni++) {
                oacc[ni][0] *= a0; oacc[ni][1] *= a0;
                oacc[ni][2] *= a1; oacc[ni][3] *= a1;
            }

#pragma unroll
            for (int kk2 = 0; kk2 < 4; kk2++) {
                uint32_t af[4];
                af[0] = h2u(s[2 * kk2][0],     s[2 * kk2][1]);
                af[1] = h2u(s[2 * kk2][2],     s[2 * kk2][3]);
                af[2] = h2u(s[2 * kk2 + 1][0], s[2 * kk2 + 1][1]);
                af[3] = h2u(s[2 * kk2 + 1][2], s[2 * kk2 + 1][3]);
#pragma unroll
                for (int nip = 0; nip < 8; nip++) {
                    int row = kk2 * 16 + (lane & 7) + (lane & 8);
                    int c16 = 2 * nip + (lane >> 4);
                    uint32_t r4[4];
                    ldsm4t(r4, Vb + row * 256 + ((c16 ^ (row & 7)) << 4));
                    mma16(oacc[2 * nip],     af, r4[0], r4[1]);
                    mma16(oacc[2 * nip + 1], af, r4[2], r4[3]);
                }
            }
        }
        __syncthreads();
    }

    const int b = bh >> 4, h = bh & 15;
    const float inv0 = 1.f / l0, inv1 = 1.f / l1;
#pragma unroll
    for (int ni = 0; ni < 16; ni++) {
        int d = ni * 8 + tg * 2;
        __half* p0 = g_aoh + ((size_t)b * S_LEN + r0) * D_MODEL + h * DHD + d;
        __half* p1 = g_aoh + ((size_t)b * S_LEN + r0 + 8) * D_MODEL + h * DHD + d;
        *(__half2*)p0 = __floats2half2_rn(oacc[ni][0] * inv0, oacc[ni][1] * inv0);
        *(__half2*)p1 = __floats2half2_rn(oacc[ni][2] * inv1, oacc[ni][3] * inv1);
    }
}

// ---------------- launch ----------------------------------------------------
extern "C" void kernel_launch(void* const* d_in, const int* in_sizes, int n_in,
                              void* d_out, int out_size)
{
    (void)in_sizes; (void)n_in; (void)out_size;
    const float* x  = (const float*)d_in[0];
    const float* fc = (const float*)d_in[1];
    const float* fs = (const float*)d_in[2];
    // d_in[3] = mask (causal, analytic)
    const float* wq = (const float*)d_in[4];
    const float* wk = (const float*)d_in[5];
    const float* wv = (const float*)d_in[6];
    const float* wo = (const float*)d_in[7];
    float* out = (float*)d_out;

    cudaFuncSetAttribute(gemm_h_kernel,
                         cudaFuncAttributeMaxDynamicSharedMemorySize, GEMM_SMEM);
    cudaFuncSetAttribute(attn_h_kernel,
                         cudaFuncAttributeMaxDynamicSharedMemorySize, ATT_SMEM);

    // 0) fp32 -> fp16 pre-pass
    dim3 gc(8192, 1, 5);
    cvt_h_kernel<<<gc, 256>>>(x, wq, wk, wv, wo);

    // 1) QKV projections + RoPE
    dim3 g1(D_MODEL / 128, M_ROWS / 128, 3);
    gemm_h_kernel<<<g1, 256, GEMM_SMEM>>>(out, fc, fs, 0);

    // 2) flash attention -> g_aoh
    dim3 g2(S_LEN / 128, NB * NH);
    attn_h_kernel<<<g2, 256, ATT_SMEM>>>();

    // 3) output projection -> d_out (fp32)
    dim3 g3(D_MODEL / 128, M_ROWS / 128, 1);
    gemm_h_kernel<<<g3, 256, GEMM_SMEM>>>(out, fc, fs, 1);
}

// round 16
// speedup vs baseline: 1.5837x; 1.5837x over previous
#include <cuda_runtime.h>
#include <cuda_fp16.h>
#include <cstdint>

#define S_LEN 2048
#define D_MODEL 2048
#define NB 2
#define NH 16
#define DHD 128
#define M_ROWS 4096

// ---------------- scratch (static __device__, allocation-guard safe) -------
__device__ __align__(16) __half g_xh[(size_t)M_ROWS * D_MODEL];
__device__ __align__(16) __half g_wh[(size_t)4 * D_MODEL * D_MODEL];  // q,k,v,o
__device__ __align__(16) __half g_qh[(size_t)M_ROWS * D_MODEL];       // [b][h][s][d]
__device__ __align__(16) __half g_kh[(size_t)M_ROWS * D_MODEL];
__device__ __align__(16) __half g_vh[(size_t)M_ROWS * D_MODEL];
__device__ __align__(16) __half g_aoh[(size_t)M_ROWS * D_MODEL];      // [b*s][h*128+d]

// ---------------- PTX helpers ----------------------------------------------
__device__ __forceinline__ void ldsm4(uint32_t* r, uint32_t a) {
    asm volatile("ldmatrix.sync.aligned.m8n8.x4.shared.b16 {%0,%1,%2,%3}, [%4];"
                 : "=r"(r[0]), "=r"(r[1]), "=r"(r[2]), "=r"(r[3]) : "r"(a));
}
__device__ __forceinline__ void ldsm4t(uint32_t* r, uint32_t a) {
    asm volatile("ldmatrix.sync.aligned.m8n8.x4.trans.shared.b16 {%0,%1,%2,%3}, [%4];"
                 : "=r"(r[0]), "=r"(r[1]), "=r"(r[2]), "=r"(r[3]) : "r"(a));
}
__device__ __forceinline__ void mma16(float* c, const uint32_t* a, uint32_t b0, uint32_t b1) {
    asm volatile(
        "mma.sync.aligned.m16n8k16.row.col.f32.f16.f16.f32 "
        "{%0,%1,%2,%3}, {%4,%5,%6,%7}, {%8,%9}, {%0,%1,%2,%3};"
        : "+f"(c[0]), "+f"(c[1]), "+f"(c[2]), "+f"(c[3])
        : "r"(a[0]), "r"(a[1]), "r"(a[2]), "r"(a[3]), "r"(b0), "r"(b1));
}
__device__ __forceinline__ void cpa16(uint32_t saddr, const void* gptr) {
    asm volatile("cp.async.cg.shared.global [%0], [%1], 16;" :: "r"(saddr), "l"(gptr));
}
#define CP_COMMIT asm volatile("cp.async.commit_group;" ::: "memory")
#define CP_WAIT0  asm volatile("cp.async.wait_group 0;" ::: "memory")
#define CP_WAIT1  asm volatile("cp.async.wait_group 1;" ::: "memory")

__device__ __forceinline__ uint32_t h2u(float a, float b) {
    __half2 h = __floats2half2_rn(a, b);
    return *reinterpret_cast<uint32_t*>(&h);
}

// ---------------- pre-pass: fp32 -> fp16 ------------------------------------
__global__ __launch_bounds__(256) void cvt_h_kernel(
    const float* __restrict__ x,
    const float* __restrict__ wq, const float* __restrict__ wk,
    const float* __restrict__ wv, const float* __restrict__ wo)
{
    const int z = blockIdx.z;
    const float* src;
    __half* dst;
    int n4;
    if (z == 0)      { src = x;  dst = g_xh; n4 = M_ROWS * D_MODEL / 4; }
    else if (z == 1) { src = wq; dst = g_wh;                                 n4 = D_MODEL * D_MODEL / 4; }
    else if (z == 2) { src = wk; dst = g_wh + (size_t)1 * D_MODEL * D_MODEL; n4 = D_MODEL * D_MODEL / 4; }
    else if (z == 3) { src = wv; dst = g_wh + (size_t)2 * D_MODEL * D_MODEL; n4 = D_MODEL * D_MODEL / 4; }
    else             { src = wo; dst = g_wh + (size_t)3 * D_MODEL * D_MODEL; n4 = D_MODEL * D_MODEL / 4; }

    int idx = blockIdx.x * 256 + threadIdx.x;
    if (idx < n4) {
        float4 v = ((const float4*)src)[idx];
        __half2* d2 = (__half2*)dst + (size_t)idx * 2;
        d2[0] = __floats2half2_rn(v.x, v.y);
        d2[1] = __floats2half2_rn(v.z, v.w);
    }
}

// ---------------- GEMM: UNCHANGED from R10 (known-good, 102us proj) ---------
// 128x128 block, BK=64, 8 warps 2x4, warp 64x32, 3-stage ring, 1 sync/chunk.
#define GEMM_SMEM (3 * 32768) /* 98304 */

__global__ __launch_bounds__(256) void gemm_h_kernel(
    float* __restrict__ Oout,
    const float* __restrict__ fc, const float* __restrict__ fs,
    int is_final)
{
    extern __shared__ __align__(16) char smraw[];
    const uint32_t sb = (uint32_t)__cvta_generic_to_shared(smraw);

    const int mode = is_final ? 3 : (int)blockIdx.z;
    const __half* A = is_final ? g_aoh : g_xh;
    const __half* W = g_wh + (size_t)mode * D_MODEL * D_MODEL;

    const int tid = threadIdx.x;
    const int warp = tid >> 5, lane = tid & 31;
    const int wm = warp >> 2, wn = warp & 3;
    const int g = lane >> 2, tg = lane & 3;
    const int bm = blockIdx.y, bn = blockIdx.x;

    const __half* Ab = A + (size_t)(bm * 128) * D_MODEL;
    const __half* Bb = W + (size_t)(bn * 128) * D_MODEL;

    float acc[4][4][4];
#pragma unroll
    for (int mi = 0; mi < 4; mi++)
#pragma unroll
        for (int ni = 0; ni < 4; ni++)
#pragma unroll
            for (int j = 0; j < 4; j++) acc[mi][ni][j] = 0.f;

    auto docopy = [&](int kc) {
        const uint32_t s0 = sb + (uint32_t)(kc % 3) * 32768;
#pragma unroll
        for (int i = 0; i < 8; i++) {
            int li = i * 256 + tid;
            if (li < 1024) {
                int r = li >> 3, c = li & 7;
                cpa16(s0 + r * 128 + ((c ^ (r & 7)) << 4),
                      Ab + (size_t)r * D_MODEL + kc * 64 + c * 8);
            } else {
                int l2 = li - 1024;
                int r = l2 >> 3, c = l2 & 7;
                cpa16(s0 + 16384 + r * 128 + ((c ^ (r & 7)) << 4),
                      Bb + (size_t)r * D_MODEL + kc * 64 + c * 8);
            }
        }
        CP_COMMIT;
    };

    const int nk = D_MODEL / 64;
    docopy(0);
    docopy(1);

    for (int kc = 0; kc < nk; kc++) {
        if (kc == nk - 1) { CP_WAIT0; } else { CP_WAIT1; }
        __syncthreads();

        if (kc + 2 < nk) docopy(kc + 2);

        const uint32_t sA = sb + (uint32_t)(kc % 3) * 32768;
        const uint32_t sBs = sA + 16384;

#pragma unroll
        for (int kk = 0; kk < 4; kk++) {
            uint32_t bf[4][2];
#pragma unroll
            for (int nip = 0; nip < 2; nip++) {
                int row = wn * 32 + nip * 16 + (lane & 7) + ((lane >> 4) << 3);
                int c8 = kk * 2 + ((lane >> 3) & 1);
                uint32_t r4[4];
                ldsm4(r4, sBs + row * 128 + ((c8 ^ (row & 7)) << 4));
                bf[2 * nip][0] = r4[0]; bf[2 * nip][1] = r4[1];
                bf[2 * nip + 1][0] = r4[2]; bf[2 * nip + 1][1] = r4[3];
            }
#pragma unroll
            for (int mi = 0; mi < 4; mi++) {
                int row = wm * 64 + mi * 16 + (lane & 15);
                int c8 = kk * 2 + (lane >> 4);
                uint32_t a4[4];
                ldsm4(a4, sA + row * 128 + ((c8 ^ (row & 7)) << 4));
#pragma unroll
                for (int ni = 0; ni < 4; ni++)
                    mma16(acc[mi][ni], a4, bf[ni][0], bf[ni][1]);
            }
        }
    }

#pragma unroll
    for (int mi = 0; mi < 4; mi++) {
#pragma unroll
        for (int ni = 0; ni < 4; ni++) {
            int m0 = bm * 128 + wm * 64 + mi * 16 + g;
            int n0 = bn * 128 + wn * 32 + ni * 8 + tg * 2;
#pragma unroll
            for (int h2 = 0; h2 < 2; h2++) {
                int m = m0 + h2 * 8;
                float e = acc[mi][ni][h2 * 2];
                float o = acc[mi][ni][h2 * 2 + 1];
                if (mode == 3) {
                    *(float2*)(Oout + (size_t)m * D_MODEL + n0) = make_float2(e, o);
                } else {
                    int b = m >> 11, s = m & 2047;
                    int hh = n0 >> 7, d = n0 & 127;
                    if (mode != 2) {
                        float c  = fc[s * 64 + (d >> 1)];
                        float sn = fs[s * 64 + (d >> 1)];
                        float e2 = e * c - o * sn;
                        float o2 = e * sn + o * c;
                        e = e2; o = o2;
                    }
                    __half* dst = (mode == 0) ? g_qh : (mode == 1) ? g_kh : g_vh;
                    size_t idx = ((size_t)(b * NH + hh) * S_LEN + s) * DHD + d;
                    *(__half2*)(dst + idx) = __floats2half2_rn(e, o);
                }
            }
        }
    }
}

// ---------------- Flash attention: R10 layout + 3-stage KV ring -------------
// Block: (qb, bh). 256 threads, 8 warps x 16 q-rows. BQ=128, BKV=64.
// Q register-resident (R10); KV in a 3-slot cp.async ring with ONE
// __syncthreads per tile (the transformation that sped the GEMM 152->102).
// smem: 3 x [K 16KB | V 16KB] = 96KB, 1 CTA/SM (regs ~155).
#define ATT_SMEM (3 * 32768) /* 98304 */

__global__ __launch_bounds__(256) void attn_h_kernel()
{
    extern __shared__ __align__(16) char smraw[];
    const uint32_t sb = (uint32_t)__cvta_generic_to_shared(smraw);

    const int bh = blockIdx.y;
    const int qb = blockIdx.x;
    const int tid = threadIdx.x;
    const int warp = tid >> 5, lane = tid & 31;
    const int g = lane >> 2, tg = lane & 3;
    const int r0 = qb * 128 + warp * 16 + g;

    const __half* kb_p = g_kh + (size_t)bh * S_LEN * DHD;
    const __half* vb_p = g_vh + (size_t)bh * S_LEN * DHD;

    // Q fragments register-resident (R10 layout)
    uint32_t qf[8][4];
    {
        const __half* q0 = g_qh + ((size_t)bh * S_LEN + r0) * DHD;
        const __half* q1 = q0 + 8 * DHD;
#pragma unroll
        for (int kk = 0; kk < 8; kk++) {
            qf[kk][0] = *(const uint32_t*)(q0 + kk * 16 + tg * 2);
            qf[kk][1] = *(const uint32_t*)(q1 + kk * 16 + tg * 2);
            qf[kk][2] = *(const uint32_t*)(q0 + kk * 16 + 8 + tg * 2);
            qf[kk][3] = *(const uint32_t*)(q1 + kk * 16 + 8 + tg * 2);
        }
    }

    float oacc[16][4];
#pragma unroll
    for (int ni = 0; ni < 16; ni++)
#pragma unroll
        for (int j = 0; j < 4; j++) oacc[ni][j] = 0.f;

    float m0v = -1e30f, m1v = -1e30f, l0 = 0.f, l1 = 0.f;
    const float scale = 0.08838834764831845f;

    auto docopy = [&](int t) {
        const uint32_t s0 = sb + (uint32_t)(t % 3) * 32768;
        const int kv0 = t * 64;
#pragma unroll
        for (int i = 0; i < 8; i++) {
            int li = i * 256 + tid;
            if (i < 4) {
                int r = li >> 4, c16 = li & 15;
                cpa16(s0 + r * 256 + ((c16 ^ (r & 7)) << 4),
                      kb_p + (size_t)(kv0 + r) * DHD + c16 * 8);
            } else {
                int l2 = li - 1024;
                int r = l2 >> 4, c16 = l2 & 15;
                cpa16(s0 + 16384 + r * 256 + ((c16 ^ (r & 7)) << 4),
                      vb_p + (size_t)(kv0 + r) * DHD + c16 * 8);
            }
        }
        CP_COMMIT;
    };

    const int nkv = 2 * (qb + 1);
    docopy(0);
    if (nkv > 1) docopy(1);

    for (int t = 0; t < nkv; t++) {
        if (t == nkv - 1) { CP_WAIT0; } else { CP_WAIT1; }
        __syncthreads();                   // tile t resident; reads of t-1 done

        if (t + 2 < nkv) docopy(t + 2);    // slot (t-1)%3 reusable post-sync

        const uint32_t Kb = sb + (uint32_t)(t % 3) * 32768;
        const uint32_t Vb = Kb + 16384;
        const int kv0 = t * 64;

        if (kv0 <= qb * 128 + warp * 16 + 15) {
            // ---- S = Q K^T ----
            float s[8][4];
#pragma unroll
            for (int ni = 0; ni < 8; ni++)
#pragma unroll
                for (int j = 0; j < 4; j++) s[ni][j] = 0.f;

#pragma unroll
            for (int kk = 0; kk < 8; kk++) {
#pragma unroll
                for (int nip = 0; nip < 4; nip++) {
                    int row = nip * 16 + (lane & 7) + ((lane >> 4) << 3);
                    int c16 = kk * 2 + ((lane >> 3) & 1);
                    uint32_t r4[4];
                    ldsm4(r4, Kb + row * 256 + ((c16 ^ (row & 7)) << 4));
                    mma16(s[2 * nip],     qf[kk], r4[0], r4[1]);
                    mma16(s[2 * nip + 1], qf[kk], r4[2], r4[3]);
                }
            }

            float mn0 = -1e30f, mn1 = -1e30f;
#pragma unroll
            for (int ni = 0; ni < 8; ni++) {
                int c = kv0 + ni * 8 + tg * 2;
                s[ni][0] = (c     <= r0)     ? s[ni][0] * scale : -1e30f;
                s[ni][1] = (c + 1 <= r0)     ? s[ni][1] * scale : -1e30f;
                s[ni][2] = (c     <= r0 + 8) ? s[ni][2] * scale : -1e30f;
                s[ni][3] = (c + 1 <= r0 + 8) ? s[ni][3] * scale : -1e30f;
                mn0 = fmaxf(mn0, fmaxf(s[ni][0], s[ni][1]));
                mn1 = fmaxf(mn1, fmaxf(s[ni][2], s[ni][3]));
            }
            mn0 = fmaxf(mn0, __shfl_xor_sync(0xffffffffu, mn0, 1));
            mn0 = fmaxf(mn0, __shfl_xor_sync(0xffffffffu, mn0, 2));
            mn1 = fmaxf(mn1, __shfl_xor_sync(0xffffffffu, mn1, 1));
            mn1 = fmaxf(mn1, __shfl_xor_sync(0xffffffffu, mn1, 2));

            float mt0 = fmaxf(m0v, mn0), mt1 = fmaxf(m1v, mn1);
            float a0 = __expf(m0v - mt0), a1 = __expf(m1v - mt1);
            m0v = mt0; m1v = mt1;

            float rs0 = 0.f, rs1 = 0.f;
#pragma unroll
            for (int ni = 0; ni < 8; ni++) {
                s[ni][0] = __expf(s[ni][0] - mt0);
                s[ni][1] = __expf(s[ni][1] - mt0);
                s[ni][2] = __expf(s[ni][2] - mt1);
                s[ni][3] = __expf(s[ni][3] - mt1);
                rs0 += s[ni][0] + s[ni][1];
                rs1 += s[ni][2] + s[ni][3];
            }
            rs0 += __shfl_xor_sync(0xffffffffu, rs0, 1);
            rs0 += __shfl_xor_sync(0xffffffffu, rs0, 2);
            rs1 += __shfl_xor_sync(0xffffffffu, rs1, 1);
            rs1 += __shfl_xor_sync(0xffffffffu, rs1, 2);
            l0 = l0 * a0 + rs0;
            l1 = l1 * a1 + rs1;

#pragma unroll
            for (int ni = 0; ni < 16; ni++) {
                oacc[ni][0] *= a0; oacc[ni][1] *= a0;
                oacc[ni][2] *= a1; oacc[ni][3] *= a1;
            }

            // ---- O += P @ V ----
#pragma unroll
            for (int kk2 = 0; kk2 < 4; kk2++) {
                uint32_t af[4];
                af[0] = h2u(s[2 * kk2][0],     s[2 * kk2][1]);
                af[1] = h2u(s[2 * kk2][2],     s[2 * kk2][3]);
                af[2] = h2u(s[2 * kk2 + 1][0], s[2 * kk2 + 1][1]);
                af[3] = h2u(s[2 * kk2 + 1][2], s[2 * kk2 + 1][3]);
#pragma unroll
                for (int nip = 0; nip < 8; nip++) {
                    int row = kk2 * 16 + (lane & 7) + (lane & 8);
                    int c16 = 2 * nip + (lane >> 4);
                    uint32_t r4[4];
                    ldsm4t(r4, Vb + row * 256 + ((c16 ^ (row & 7)) << 4));
                    mma16(oacc[2 * nip],     af, r4[0], r4[1]);
                    mma16(oacc[2 * nip + 1], af, r4[2], r4[3]);
                }
            }
        }
    }

    const int b = bh >> 4, h = bh & 15;
    const float inv0 = 1.f / l0, inv1 = 1.f / l1;
#pragma unroll
    for (int ni = 0; ni < 16; ni++) {
        int d = ni * 8 + tg * 2;
        __half* p0 = g_aoh + ((size_t)b * S_LEN + r0) * D_MODEL + h * DHD + d;
        __half* p1 = g_aoh + ((size_t)b * S_LEN + r0 + 8) * D_MODEL + h * DHD + d;
        *(__half2*)p0 = __floats2half2_rn(oacc[ni][0] * inv0, oacc[ni][1] * inv0);
        *(__half2*)p1 = __floats2half2_rn(oacc[ni][2] * inv1, oacc[ni][3] * inv1);
    }
}

// ---------------- launch ----------------------------------------------------
extern "C" void kernel_launch(void* const* d_in, const int* in_sizes, int n_in,
                              void* d_out, int out_size)
{
    (void)in_sizes; (void)n_in; (void)out_size;
    const float* x  = (const float*)d_in[0];
    const float* fc = (const float*)d_in[1];
    const float* fs = (const float*)d_in[2];
    // d_in[3] = mask (causal, analytic)
    const float* wq = (const float*)d_in[4];
    const float* wk = (const float*)d_in[5];
    const float* wv = (const float*)d_in[6];
    const float* wo = (const float*)d_in[7];
    float* out = (float*)d_out;

    cudaFuncSetAttribute(gemm_h_kernel,
                         cudaFuncAttributeMaxDynamicSharedMemorySize, GEMM_SMEM);
    cudaFuncSetAttribute(attn_h_kernel,
                         cudaFuncAttributeMaxDynamicSharedMemorySize, ATT_SMEM);

    // 0) fp32 -> fp16 pre-pass
    dim3 gc(8192, 1, 5);
    cvt_h_kernel<<<gc, 256>>>(x, wq, wk, wv, wo);

    // 1) QKV projections + RoPE
    dim3 g1(D_MODEL / 128, M_ROWS / 128, 3);
    gemm_h_kernel<<<g1, 256, GEMM_SMEM>>>(out, fc, fs, 0);

    // 2) flash attention -> g_aoh
    dim3 g2(S_LEN / 128, NB * NH);
    attn_h_kernel<<<g2, 256, ATT_SMEM>>>();

    // 3) output projection -> d_out (fp32)
    dim3 g3(D_MODEL / 128, M_ROWS / 128, 1);
    gemm_h_kernel<<<g3, 256, GEMM_SMEM>>>(out, fc, fs, 1);
}